// round 13
// baseline (speedup 1.0000x reference)
#include <cuda_runtime.h>
#include <math.h>

#define S_LEN  2048
#define B_SZ   4
#define DMODEL 512
#define DK     64
#define BM     128      // query rows per attention block (== threads)
#define KC     256      // keys per split-KV chunk
#define SUBK   64       // keys per SMEM subtile
#define NT     (S_LEN / BM)   // 16 query tiles per batch
#define MAXCH  (S_LEN / KC)   // 8 chunks max

typedef unsigned long long u64;

// ---- packed fp32x2 helpers (ptxas never emits FFMA2 from C++; PTX only) ----
__device__ __forceinline__ u64 pack2(float lo, float hi) {
    u64 r; asm("mov.b64 %0, {%1, %2};" : "=l"(r) : "f"(lo), "f"(hi)); return r;
}
__device__ __forceinline__ void ffma2(u64& d, u64 a, u64 b) {
    asm("fma.rn.f32x2 %0, %1, %2, %0;" : "+l"(d) : "l"(a), "l"(b));
}
__device__ __forceinline__ void fmul2(u64& d, u64 a) {
    asm("mul.rn.f32x2 %0, %0, %1;" : "+l"(d) : "l"(a));
}
__device__ __forceinline__ float2 unpack2(u64 v) {
    float2 f; asm("mov.b64 {%0, %1}, %2;" : "=f"(f.x), "=f"(f.y) : "l"(v)); return f;
}

// ------------------------- scratch (no mallocs allowed) -------------------------
__device__ float g_q   [B_SZ * S_LEN * DK];
__device__ float g_k   [B_SZ * S_LEN * DK];
__device__ float g_v   [B_SZ * S_LEN * DK];
__device__ float g_ho  [B_SZ * S_LEN * DK];
__device__ float g_weff[DK * DMODEL];
__device__ float g_po  [(size_t)B_SZ * NT * MAXCH * BM * DK];
__device__ float g_pml [(size_t)B_SZ * NT * MAXCH * BM * 2];

// ------------------------- 1) fused q/k/v projections -------------------------
// GEMM: out[8192,64] = X[8192,512] @ W[512,64] + b.  (R7 form — known best)
__global__ __launch_bounds__(256) void proj_kernel(
    const float* __restrict__ Q, const float* __restrict__ K, const float* __restrict__ V,
    const float* __restrict__ WQ, const float* __restrict__ bQ,
    const float* __restrict__ WK, const float* __restrict__ bK,
    const float* __restrict__ WV, const float* __restrict__ bV)
{
    const float* X; const float* W; const float* bias; float* out;
    if (blockIdx.z == 0)      { X = Q; W = WQ; bias = bQ; out = g_q; }
    else if (blockIdx.z == 1) { X = K; W = WK; bias = bK; out = g_k; }
    else                      { X = V; W = WV; bias = bV; out = g_v; }

    __shared__ float Xs[64][33];   // padded: avoid bank conflict on row reads
    __shared__ float Ws[32][64];

    const int tid = threadIdx.x;
    const int tx = tid & 15, ty = tid >> 4;
    const int m0 = blockIdx.x * 64;

    u64 acc2[4][2];
    #pragma unroll
    for (int i = 0; i < 4; i++) { acc2[i][0] = 0ull; acc2[i][1] = 0ull; }

    for (int k0 = 0; k0 < DMODEL; k0 += 32) {
        __syncthreads();
        #pragma unroll
        for (int it = 0; it < 2; it++) {
            int idx = tid + it * 256;          // 0..511
            int row = idx >> 3;                // 8 float4 per row
            int c4  = idx & 7;
            float4 v4 = *(const float4*)(X + (size_t)(m0 + row) * DMODEL + k0 + c4 * 4);
            Xs[row][c4 * 4 + 0] = v4.x; Xs[row][c4 * 4 + 1] = v4.y;
            Xs[row][c4 * 4 + 2] = v4.z; Xs[row][c4 * 4 + 3] = v4.w;
        }
        #pragma unroll
        for (int it = 0; it < 2; it++) {
            int idx = tid + it * 256;
            int row = idx >> 4;                // 16 float4 per row
            int c4  = idx & 15;
            float4 v4 = *(const float4*)(W + (size_t)(k0 + row) * DK + c4 * 4);
            *(float4*)&Ws[row][c4 * 4] = v4;
        }
        __syncthreads();

        #pragma unroll
        for (int kk = 0; kk < 32; kk++) {
            u64 pa0 = pack2(Xs[ty * 4 + 0][kk], Xs[ty * 4 + 0][kk]);
            u64 pa1 = pack2(Xs[ty * 4 + 1][kk], Xs[ty * 4 + 1][kk]);
            u64 pa2 = pack2(Xs[ty * 4 + 2][kk], Xs[ty * 4 + 2][kk]);
            u64 pa3 = pack2(Xs[ty * 4 + 3][kk], Xs[ty * 4 + 3][kk]);
            ulonglong2 b2 = *(const ulonglong2*)&Ws[kk][tx * 4];
            ffma2(acc2[0][0], pa0, b2.x); ffma2(acc2[0][1], pa0, b2.y);
            ffma2(acc2[1][0], pa1, b2.x); ffma2(acc2[1][1], pa1, b2.y);
            ffma2(acc2[2][0], pa2, b2.x); ffma2(acc2[2][1], pa2, b2.y);
            ffma2(acc2[3][0], pa3, b2.x); ffma2(acc2[3][1], pa3, b2.y);
        }
    }

    float4 bb = *(const float4*)&bias[tx * 4];
    #pragma unroll
    for (int i = 0; i < 4; i++) {
        float2 c0 = unpack2(acc2[i][0]);
        float2 c1 = unpack2(acc2[i][1]);
        float4 r = make_float4(c0.x + bb.x, c0.y + bb.y, c1.x + bb.z, c1.y + bb.w);
        *(float4*)&out[(size_t)(m0 + ty * 4 + i) * DK + tx * 4] = r;
    }
}

// ------------------------- 2) W_eff = sum over 8 head-blocks of Wo_w ----------
__global__ void weff_kernel(const float* __restrict__ Wo) {
    int idx = blockIdx.x * 256 + threadIdx.x;  // 64*512 = 32768 elements
    int r = idx >> 9;
    int c = idx & 511;
    float s = 0.f;
    #pragma unroll
    for (int h = 0; h < 8; h++) s += Wo[(size_t)((h << 6) + r) * DMODEL + c];
    g_weff[idx] = s;
}

// ------------------------- 3) split-KV flash attention partials ---------------
// One thread owns one query row: q[64], o[64] packed as f32x2 in registers.
// R7 loop body EXACTLY; min-blocks=3 caps regs at ~170 -> 12 warps/SM (vs ~8).
__global__ __launch_bounds__(128, 3) void attn_partial_kernel() {
    const int b = blockIdx.z;
    const int t = blockIdx.y;
    const int chunk = blockIdx.x;
    const int kbeg = chunk * KC;
    const int kend = min(kbeg + KC, (t + 1) * BM);
    if (kbeg >= kend) return;  // uniform across block (no sync before this)

    const int tid = threadIdx.x;
    const int qrow = t * BM + tid;

    const float* qptr = g_q + ((size_t)b * S_LEN + qrow) * DK;
    u64 q2[32];
    {
        const ulonglong2* qp2 = (const ulonglong2*)qptr;
        #pragma unroll
        for (int i = 0; i < 16; i++) { ulonglong2 v = qp2[i]; q2[2*i] = v.x; q2[2*i+1] = v.y; }
    }

    __shared__ float Ks[SUBK][DK];
    __shared__ float Vs[SUBK][DK];

    float m = -INFINITY, l = 0.f;
    u64 o2[32];
    #pragma unroll
    for (int i = 0; i < 32; i++) o2[i] = 0ull;   // bit pattern {0f,0f}

    const int lrow = tid >> 1, half = tid & 1;

    for (int ks = kbeg; ks < kend; ks += SUBK) {
        __syncthreads();
        {   // cooperative load: 64 rows x 64 floats each for K and V
            const float4* kg = (const float4*)(g_k + ((size_t)b * S_LEN + ks + lrow) * DK + half * 32);
            const float4* vg = (const float4*)(g_v + ((size_t)b * S_LEN + ks + lrow) * DK + half * 32);
            float4* kd = (float4*)&Ks[lrow][half * 32];
            float4* vd = (float4*)&Vs[lrow][half * 32];
            #pragma unroll
            for (int i = 0; i < 8; i++) kd[i] = kg[i];
            #pragma unroll
            for (int i = 0; i < 8; i++) vd[i] = vg[i];
        }
        __syncthreads();

        const int jmax = min(SUBK, qrow - ks + 1);   // causal bound for this row
        #pragma unroll 2
        for (int j = 0; j < jmax; j++) {
            const ulonglong2* kk2 = (const ulonglong2*)&Ks[j][0];
            u64 a0 = 0ull, a1 = 0ull, a2 = 0ull, a3 = 0ull;
            #pragma unroll
            for (int i = 0; i < 4; i++) {
                ulonglong2 ka = kk2[4*i + 0]; ffma2(a0, q2[8*i + 0], ka.x); ffma2(a1, q2[8*i + 1], ka.y);
                ulonglong2 kb = kk2[4*i + 1]; ffma2(a2, q2[8*i + 2], kb.x); ffma2(a3, q2[8*i + 3], kb.y);
                ulonglong2 kc = kk2[4*i + 2]; ffma2(a0, q2[8*i + 4], kc.x); ffma2(a1, q2[8*i + 5], kc.y);
                ulonglong2 kd = kk2[4*i + 3]; ffma2(a2, q2[8*i + 6], kd.x); ffma2(a3, q2[8*i + 7], kd.y);
            }
            float2 f0 = unpack2(a0), f1 = unpack2(a1), f2 = unpack2(a2), f3 = unpack2(a3);
            float s = (((f0.x + f0.y) + (f1.x + f1.y)) + ((f2.x + f2.y) + (f3.x + f3.y))) * 0.125f;

            if (s > m) {              // rare online-softmax rescale
                float cor = __expf(m - s);   // m=-inf first time -> 0, o already 0
                l *= cor;
                u64 cor2 = pack2(cor, cor);
                #pragma unroll
                for (int d = 0; d < 32; d++) fmul2(o2[d], cor2);
                m = s;
            }
            float p = __expf(s - m);
            l += p;
            u64 pp = pack2(p, p);
            const ulonglong2* vv2 = (const ulonglong2*)&Vs[j][0];
            #pragma unroll
            for (int i = 0; i < 16; i++) {
                ulonglong2 v = vv2[i];
                ffma2(o2[2*i + 0], pp, v.x);
                ffma2(o2[2*i + 1], pp, v.y);
            }
        }
    }

    const size_t base = (((size_t)b * NT + t) * MAXCH + chunk) * BM + tid;
    ulonglong2* po2 = (ulonglong2*)(g_po + base * DK);
    #pragma unroll
    for (int i = 0; i < 16; i++) {
        ulonglong2 v; v.x = o2[2*i]; v.y = o2[2*i + 1];
        po2[i] = v;
    }
    *(float2*)&g_pml[base * 2] = make_float2(m, l);
}

// ------------------------- 4) merge split-KV partials -------------------------
// One thread per (row, float4): 2048 threads/tile. grid (NT*2, B), block 1024.
__global__ __launch_bounds__(1024) void attn_merge_kernel() {
    const int b = blockIdx.y;
    const int t = blockIdx.x >> 1;
    const int tid = threadIdx.x;
    const int row = (blockIdx.x & 1) * 64 + (tid >> 4);  // 0..127
    const int f4  = tid & 15;                            // float4 index in DK
    const int nch = ((t + 1) * BM + KC - 1) / KC;        // active chunks
    const size_t base0 = (((size_t)b * NT + t) * MAXCH) * BM + row;

    float mc[MAXCH], lc[MAXCH];
    float mstar = -INFINITY;
    for (int c = 0; c < nch; c++) {
        float2 ml = *(const float2*)&g_pml[(base0 + (size_t)c * BM) * 2];
        mc[c] = ml.x; lc[c] = ml.y;
        mstar = fmaxf(mstar, ml.x);
    }

    float lsum = 0.f;
    float4 o = make_float4(0.f, 0.f, 0.f, 0.f);

    for (int c = 0; c < nch; c++) {
        float w = __expf(mc[c] - mstar);
        lsum += lc[c] * w;
        float4 v4 = *(const float4*)(g_po + (base0 + (size_t)c * BM) * DK + f4 * 4);
        o.x = fmaf(w, v4.x, o.x);
        o.y = fmaf(w, v4.y, o.y);
        o.z = fmaf(w, v4.z, o.z);
        o.w = fmaf(w, v4.w, o.w);
    }
    float inv = 1.f / lsum;
    *(float4*)(g_ho + ((size_t)b * S_LEN + t * BM + row) * DK + f4 * 4) =
        make_float4(o.x * inv, o.y * inv, o.z * inv, o.w * inv);
}

// ------------------------- 5) output GEMM: ho @ W_eff + Wo_b ------------------
// out[8192,512] = ho[8192,64] @ g_weff[64,512] + b. (R7 form — known best)
__global__ __launch_bounds__(256) void outproj_kernel(
    const float* __restrict__ Wo_b, float* __restrict__ out)
{
    __shared__ float As[64][65];
    __shared__ float Bs[64][64];

    const int tid = threadIdx.x;
    const int tx = tid & 15, ty = tid >> 4;
    const int m0 = blockIdx.x * 64;
    const int n0 = blockIdx.y * 64;

    #pragma unroll
    for (int it = 0; it < 4; it++) {
        int idx = tid + it * 256;
        int row = idx >> 4;
        int c4  = idx & 15;
        float4 v4 = *(const float4*)(g_ho + (size_t)(m0 + row) * DK + c4 * 4);
        As[row][c4 * 4 + 0] = v4.x; As[row][c4 * 4 + 1] = v4.y;
        As[row][c4 * 4 + 2] = v4.z; As[row][c4 * 4 + 3] = v4.w;
    }
    #pragma unroll
    for (int it = 0; it < 4; it++) {
        int idx = tid + it * 256;
        int row = idx >> 4;
        int c4  = idx & 15;
        float4 v4 = *(const float4*)(g_weff + (size_t)row * DMODEL + n0 + c4 * 4);
        *(float4*)&Bs[row][c4 * 4] = v4;
    }
    __syncthreads();

    u64 acc2[4][2];
    #pragma unroll
    for (int i = 0; i < 4; i++) { acc2[i][0] = 0ull; acc2[i][1] = 0ull; }

    #pragma unroll
    for (int kk = 0; kk < 64; kk++) {
        u64 pa0 = pack2(As[ty * 4 + 0][kk], As[ty * 4 + 0][kk]);
        u64 pa1 = pack2(As[ty * 4 + 1][kk], As[ty * 4 + 1][kk]);
        u64 pa2 = pack2(As[ty * 4 + 2][kk], As[ty * 4 + 2][kk]);
        u64 pa3 = pack2(As[ty * 4 + 3][kk], As[ty * 4 + 3][kk]);
        ulonglong2 b2 = *(const ulonglong2*)&Bs[kk][tx * 4];
        ffma2(acc2[0][0], pa0, b2.x); ffma2(acc2[0][1], pa0, b2.y);
        ffma2(acc2[1][0], pa1, b2.x); ffma2(acc2[1][1], pa1, b2.y);
        ffma2(acc2[2][0], pa2, b2.x); ffma2(acc2[2][1], pa2, b2.y);
        ffma2(acc2[3][0], pa3, b2.x); ffma2(acc2[3][1], pa3, b2.y);
    }

    float4 bb = *(const float4*)&Wo_b[n0 + tx * 4];
    #pragma unroll
    for (int i = 0; i < 4; i++) {
        float2 c0 = unpack2(acc2[i][0]);
        float2 c1 = unpack2(acc2[i][1]);
        float4 r = make_float4(c0.x + bb.x, c0.y + bb.y, c1.x + bb.z, c1.y + bb.w);
        *(float4*)&out[(size_t)(m0 + ty * 4 + i) * DMODEL + n0 + tx * 4] = r;
    }
}

// ------------------------- launch --------------------------------------------
extern "C" void kernel_launch(void* const* d_in, const int* in_sizes, int n_in,
                              void* d_out, int out_size) {
    const float* Q    = (const float*)d_in[0];
    const float* K    = (const float*)d_in[1];
    const float* V    = (const float*)d_in[2];
    const float* WQ_w = (const float*)d_in[3];
    const float* WQ_b = (const float*)d_in[4];
    const float* WK_w = (const float*)d_in[5];
    const float* WK_b = (const float*)d_in[6];
    const float* WV_w = (const float*)d_in[7];
    const float* WV_b = (const float*)d_in[8];
    const float* Wo_w = (const float*)d_in[9];
    const float* Wo_b = (const float*)d_in[10];
    float* out = (float*)d_out;

    dim3 gproj(B_SZ * S_LEN / 64, 1, 3);
    proj_kernel<<<gproj, 256>>>(Q, K, V, WQ_w, WQ_b, WK_w, WK_b, WV_w, WV_b);

    weff_kernel<<<(DK * DMODEL) / 256, 256>>>(Wo_w);

    dim3 gattn(MAXCH, NT, B_SZ);
    attn_partial_kernel<<<gattn, 128>>>();

    dim3 gmerge(NT * 2, B_SZ);
    attn_merge_kernel<<<gmerge, 1024>>>();

    dim3 gout(B_SZ * S_LEN / 64, DMODEL / 64);
    outproj_kernel<<<gout, 256>>>(Wo_b, out);
}

// round 15
// speedup vs baseline: 2.2728x; 2.2728x over previous
#include <cuda_runtime.h>
#include <math.h>
#include <stdint.h>

#define S_LEN  2048
#define B_SZ   4
#define DMODEL 512
#define DK     64
#define BM     128      // query rows per attention block
#define KC     256      // keys per split-KV chunk
#define NT     (S_LEN / BM)   // 16 query tiles per batch
#define MAXCH  (S_LEN / KC)   // 8 chunks max

typedef unsigned long long u64;

// ---- packed fp32x2 helpers (ptxas never emits FFMA2 from C++; PTX only) ----
__device__ __forceinline__ u64 pack2(float lo, float hi) {
    u64 r; asm("mov.b64 %0, {%1, %2};" : "=l"(r) : "f"(lo), "f"(hi)); return r;
}
__device__ __forceinline__ void ffma2(u64& d, u64 a, u64 b) {
    asm("fma.rn.f32x2 %0, %1, %2, %0;" : "+l"(d) : "l"(a), "l"(b));
}
__device__ __forceinline__ float2 unpack2(u64 v) {
    float2 f; asm("mov.b64 {%0, %1}, %2;" : "=f"(f.x), "=f"(f.y) : "l"(v)); return f;
}

// ---- tf32 mma.sync m16n8k8 (row.col), fp32 accumulate ----
__device__ __forceinline__ void mma_tf32(float* c, const uint32_t* a, uint32_t b0, uint32_t b1) {
    asm("mma.sync.aligned.m16n8k8.row.col.f32.tf32.tf32.f32 "
        "{%0,%1,%2,%3}, {%4,%5,%6,%7}, {%8,%9}, {%0,%1,%2,%3};"
        : "+f"(c[0]), "+f"(c[1]), "+f"(c[2]), "+f"(c[3])
        : "r"(a[0]), "r"(a[1]), "r"(a[2]), "r"(a[3]), "r"(b0), "r"(b1));
}

// ------------------------- scratch (no mallocs allowed) -------------------------
__device__ float g_q   [B_SZ * S_LEN * DK];
__device__ float g_k   [B_SZ * S_LEN * DK];
__device__ float g_v   [B_SZ * S_LEN * DK];
__device__ float g_ho  [B_SZ * S_LEN * DK];
__device__ float g_weff[DK * DMODEL];
__device__ float g_po  [(size_t)B_SZ * NT * MAXCH * BM * DK];
__device__ float g_pml [(size_t)B_SZ * NT * MAXCH * BM * 2];

// ------------------------- 1) fused q/k/v projections -------------------------
// GEMM: out[8192,64] = X[8192,512] @ W[512,64] + b.  (R7 form — known best)
__global__ __launch_bounds__(256) void proj_kernel(
    const float* __restrict__ Q, const float* __restrict__ K, const float* __restrict__ V,
    const float* __restrict__ WQ, const float* __restrict__ bQ,
    const float* __restrict__ WK, const float* __restrict__ bK,
    const float* __restrict__ WV, const float* __restrict__ bV)
{
    const float* X; const float* W; const float* bias; float* out;
    if (blockIdx.z == 0)      { X = Q; W = WQ; bias = bQ; out = g_q; }
    else if (blockIdx.z == 1) { X = K; W = WK; bias = bK; out = g_k; }
    else                      { X = V; W = WV; bias = bV; out = g_v; }

    __shared__ float Xs[64][33];
    __shared__ float Ws[32][64];

    const int tid = threadIdx.x;
    const int tx = tid & 15, ty = tid >> 4;
    const int m0 = blockIdx.x * 64;

    u64 acc2[4][2];
    #pragma unroll
    for (int i = 0; i < 4; i++) { acc2[i][0] = 0ull; acc2[i][1] = 0ull; }

    for (int k0 = 0; k0 < DMODEL; k0 += 32) {
        __syncthreads();
        #pragma unroll
        for (int it = 0; it < 2; it++) {
            int idx = tid + it * 256;
            int row = idx >> 3;
            int c4  = idx & 7;
            float4 v4 = *(const float4*)(X + (size_t)(m0 + row) * DMODEL + k0 + c4 * 4);
            Xs[row][c4 * 4 + 0] = v4.x; Xs[row][c4 * 4 + 1] = v4.y;
            Xs[row][c4 * 4 + 2] = v4.z; Xs[row][c4 * 4 + 3] = v4.w;
        }
        #pragma unroll
        for (int it = 0; it < 2; it++) {
            int idx = tid + it * 256;
            int row = idx >> 4;
            int c4  = idx & 15;
            float4 v4 = *(const float4*)(W + (size_t)(k0 + row) * DK + c4 * 4);
            *(float4*)&Ws[row][c4 * 4] = v4;
        }
        __syncthreads();

        #pragma unroll
        for (int kk = 0; kk < 32; kk++) {
            u64 pa0 = pack2(Xs[ty * 4 + 0][kk], Xs[ty * 4 + 0][kk]);
            u64 pa1 = pack2(Xs[ty * 4 + 1][kk], Xs[ty * 4 + 1][kk]);
            u64 pa2 = pack2(Xs[ty * 4 + 2][kk], Xs[ty * 4 + 2][kk]);
            u64 pa3 = pack2(Xs[ty * 4 + 3][kk], Xs[ty * 4 + 3][kk]);
            ulonglong2 b2 = *(const ulonglong2*)&Ws[kk][tx * 4];
            ffma2(acc2[0][0], pa0, b2.x); ffma2(acc2[0][1], pa0, b2.y);
            ffma2(acc2[1][0], pa1, b2.x); ffma2(acc2[1][1], pa1, b2.y);
            ffma2(acc2[2][0], pa2, b2.x); ffma2(acc2[2][1], pa2, b2.y);
            ffma2(acc2[3][0], pa3, b2.x); ffma2(acc2[3][1], pa3, b2.y);
        }
    }

    float4 bb = *(const float4*)&bias[tx * 4];
    #pragma unroll
    for (int i = 0; i < 4; i++) {
        float2 c0 = unpack2(acc2[i][0]);
        float2 c1 = unpack2(acc2[i][1]);
        float4 r = make_float4(c0.x + bb.x, c0.y + bb.y, c1.x + bb.z, c1.y + bb.w);
        *(float4*)&out[(size_t)(m0 + ty * 4 + i) * DK + tx * 4] = r;
    }
}

// ------------------------- 2) W_eff = sum over 8 head-blocks of Wo_w ----------
__global__ void weff_kernel(const float* __restrict__ Wo) {
    int idx = blockIdx.x * 256 + threadIdx.x;
    int r = idx >> 9;
    int c = idx & 511;
    float s = 0.f;
    #pragma unroll
    for (int h = 0; h < 8; h++) s += Wo[(size_t)((h << 6) + r) * DMODEL + c];
    g_weff[idx] = s;
}

// ------------------------- 3) split-KV flash attention partials (tf32 mma) ----
// Block: 128 q-rows, 4 warps x 32 rows. 32-key subtiles. S and PV via
// mma.sync.m16n8k8 tf32. SMEM strides chosen conflict-free for fragment loads.
__global__ __launch_bounds__(128) void attn_partial_kernel() {
    const int b = blockIdx.z, t = blockIdx.y, chunk = blockIdx.x;
    const int kbeg = chunk * KC;
    const int kend = min(kbeg + KC, (t + 1) * BM);
    if (kbeg >= kend) return;   // uniform across block (no sync before this)

    const int tid  = threadIdx.x;
    const int w    = tid >> 5;
    const int lane = tid & 31;
    const int g    = lane >> 2;     // groupID (row within fragment)
    const int q    = lane & 3;      // threadID-in-group
    const int wrow = t * BM + w * 32;   // first global q-row of this warp

    // Q fragments (raw f32 bits as tf32), persistent across subtiles
    uint32_t Qf[2][8][4];
    {
        const float* qb = g_q + ((size_t)b * S_LEN + wrow) * DK;
        #pragma unroll
        for (int mt = 0; mt < 2; mt++)
            #pragma unroll
            for (int kt = 0; kt < 8; kt++) {
                int r = mt * 16 + g, c = kt * 8 + q;
                Qf[mt][kt][0] = __float_as_uint(qb[(size_t)r * DK + c]);
                Qf[mt][kt][1] = __float_as_uint(qb[(size_t)(r + 8) * DK + c]);
                Qf[mt][kt][2] = __float_as_uint(qb[(size_t)r * DK + c + 4]);
                Qf[mt][kt][3] = __float_as_uint(qb[(size_t)(r + 8) * DK + c + 4]);
            }
    }

    __shared__ float Ks[32][68];    // 68: (4g+q) mod 32 distinct -> conflict-free B-frags
    __shared__ float Vs[32][72];    // 72: (8q+g) mod 32 distinct -> conflict-free B-frags
    __shared__ float Ps[128][36];   // 36: (4g+q) mod 32 distinct -> conflict-free A-frags

    float O[2][8][4];
    #pragma unroll
    for (int mt = 0; mt < 2; mt++)
        #pragma unroll
        for (int nd = 0; nd < 8; nd++)
            #pragma unroll
            for (int c = 0; c < 4; c++) O[mt][nd][c] = 0.f;
    float mS[4] = {-INFINITY, -INFINITY, -INFINITY, -INFINITY};
    float lS[4] = {0.f, 0.f, 0.f, 0.f};

    const int lrow = tid >> 2, quar = tid & 3;

    for (int ks = kbeg; ks < kend; ks += 32) {
        __syncthreads();
        {   // cooperative load: 32 keys x 64 floats for K and V
            const float4* kg = (const float4*)(g_k + ((size_t)b * S_LEN + ks + lrow) * DK + quar * 16);
            const float4* vg = (const float4*)(g_v + ((size_t)b * S_LEN + ks + lrow) * DK + quar * 16);
            #pragma unroll
            for (int i = 0; i < 4; i++) *(float4*)&Ks[lrow][quar * 16 + i * 4] = kg[i];
            #pragma unroll
            for (int i = 0; i < 4; i++) *(float4*)&Vs[lrow][quar * 16 + i * 4] = vg[i];
        }
        __syncthreads();

        if (ks > wrow + 31) continue;   // keys entirely above this warp's rows (warp-uniform)

        // ---- S = Q @ K^T ----
        float S[2][4][4];
        #pragma unroll
        for (int mt = 0; mt < 2; mt++)
            #pragma unroll
            for (int nt = 0; nt < 4; nt++)
                #pragma unroll
                for (int c = 0; c < 4; c++) S[mt][nt][c] = 0.f;

        #pragma unroll
        for (int nt = 0; nt < 4; nt++)
            #pragma unroll
            for (int kt = 0; kt < 8; kt++) {
                uint32_t b0 = __float_as_uint(Ks[nt * 8 + g][kt * 8 + q]);
                uint32_t b1 = __float_as_uint(Ks[nt * 8 + g][kt * 8 + q + 4]);
                mma_tf32(S[0][nt], Qf[0][kt], b0, b1);
                mma_tf32(S[1][nt], Qf[1][kt], b0, b1);
            }

        // scale + causal mask (only the aligned diagonal subtile needs masking)
        #pragma unroll
        for (int mt = 0; mt < 2; mt++)
            #pragma unroll
            for (int nt = 0; nt < 4; nt++)
                #pragma unroll
                for (int c = 0; c < 4; c++) S[mt][nt][c] *= 0.125f;  // 1/sqrt(64)
        if (ks == wrow) {
            #pragma unroll
            for (int mt = 0; mt < 2; mt++)
                #pragma unroll
                for (int nt = 0; nt < 4; nt++) {
                    int r0 = mt * 16 + g, k0 = nt * 8 + 2 * q;
                    if (k0     > r0    ) S[mt][nt][0] = -INFINITY;
                    if (k0 + 1 > r0    ) S[mt][nt][1] = -INFINITY;
                    if (k0     > r0 + 8) S[mt][nt][2] = -INFINITY;
                    if (k0 + 1 > r0 + 8) S[mt][nt][3] = -INFINITY;
                }
        }

        // ---- online softmax per row-slot (4 slots: mt x {g, g+8}) ----
        #pragma unroll
        for (int mt = 0; mt < 2; mt++)
            #pragma unroll
            for (int hi = 0; hi < 2; hi++) {
                const int si = mt * 2 + hi;
                const int i0 = hi * 2;
                float rmax = fmaxf(fmaxf(S[mt][0][i0], S[mt][0][i0 + 1]),
                                   fmaxf(S[mt][1][i0], S[mt][1][i0 + 1]));
                rmax = fmaxf(rmax, fmaxf(fmaxf(S[mt][2][i0], S[mt][2][i0 + 1]),
                                         fmaxf(S[mt][3][i0], S[mt][3][i0 + 1])));
                rmax = fmaxf(rmax, __shfl_xor_sync(0xFFFFFFFFu, rmax, 1));
                rmax = fmaxf(rmax, __shfl_xor_sync(0xFFFFFFFFu, rmax, 2));
                float mnew = fmaxf(mS[si], rmax);
                float cor  = __expf(mS[si] - mnew);   // first subtile: exp(-inf)=0, O already 0
                mS[si] = mnew;
                float rsum = 0.f;
                #pragma unroll
                for (int nt = 0; nt < 4; nt++) {
                    float p0 = __expf(S[mt][nt][i0]     - mnew);
                    float p1 = __expf(S[mt][nt][i0 + 1] - mnew);
                    S[mt][nt][i0] = p0; S[mt][nt][i0 + 1] = p1;
                    rsum += p0 + p1;
                }
                rsum += __shfl_xor_sync(0xFFFFFFFFu, rsum, 1);
                rsum += __shfl_xor_sync(0xFFFFFFFFu, rsum, 2);
                lS[si] = lS[si] * cor + rsum;
                #pragma unroll
                for (int nd = 0; nd < 8; nd++) { O[mt][nd][i0] *= cor; O[mt][nd][i0 + 1] *= cor; }
            }

        // ---- P: C-layout regs -> SMEM (warp-private rows) ----
        #pragma unroll
        for (int mt = 0; mt < 2; mt++)
            #pragma unroll
            for (int nt = 0; nt < 4; nt++) {
                int r = w * 32 + mt * 16 + g;
                *(float2*)&Ps[r][nt * 8 + 2 * q]     = make_float2(S[mt][nt][0], S[mt][nt][1]);
                *(float2*)&Ps[r + 8][nt * 8 + 2 * q] = make_float2(S[mt][nt][2], S[mt][nt][3]);
            }
        __syncwarp();

        // ---- O += P @ V ----
        #pragma unroll
        for (int kp = 0; kp < 4; kp++) {
            uint32_t A[2][4];
            #pragma unroll
            for (int mt = 0; mt < 2; mt++) {
                int r = w * 32 + mt * 16 + g, c = kp * 8 + q;
                A[mt][0] = __float_as_uint(Ps[r][c]);
                A[mt][1] = __float_as_uint(Ps[r + 8][c]);
                A[mt][2] = __float_as_uint(Ps[r][c + 4]);
                A[mt][3] = __float_as_uint(Ps[r + 8][c + 4]);
            }
            #pragma unroll
            for (int nd = 0; nd < 8; nd++) {
                uint32_t b0 = __float_as_uint(Vs[kp * 8 + q][nd * 8 + g]);
                uint32_t b1 = __float_as_uint(Vs[kp * 8 + q + 4][nd * 8 + g]);
                mma_tf32(O[0][nd], A[0], b0, b1);
                mma_tf32(O[1][nd], A[1], b0, b1);
            }
        }
    }

    // ---- epilogue: write partial O, (m, l) ----
    const size_t baseRow = ((size_t)((b * NT + t) * MAXCH + chunk)) * BM;
    #pragma unroll
    for (int mt = 0; mt < 2; mt++)
        #pragma unroll
        for (int nd = 0; nd < 8; nd++) {
            int r = w * 32 + mt * 16 + g;
            float* p0 = g_po + (baseRow + r) * DK + nd * 8 + 2 * q;
            float* p1 = g_po + (baseRow + r + 8) * DK + nd * 8 + 2 * q;
            *(float2*)p0 = make_float2(O[mt][nd][0], O[mt][nd][1]);
            *(float2*)p1 = make_float2(O[mt][nd][2], O[mt][nd][3]);
        }
    if (q == 0) {
        #pragma unroll
        for (int mt = 0; mt < 2; mt++)
            #pragma unroll
            for (int hi = 0; hi < 2; hi++) {
                int r = w * 32 + mt * 16 + hi * 8 + g;
                *(float2*)&g_pml[(baseRow + r) * 2] = make_float2(mS[mt * 2 + hi], lS[mt * 2 + hi]);
            }
    }
}

// ------------------------- 4) merge split-KV partials -------------------------
// One thread per (row, float4): 2048 threads/tile. grid (NT*2, B), block 1024.
__global__ __launch_bounds__(1024) void attn_merge_kernel() {
    const int b = blockIdx.y;
    const int t = blockIdx.x >> 1;
    const int tid = threadIdx.x;
    const int row = (blockIdx.x & 1) * 64 + (tid >> 4);
    const int f4  = tid & 15;
    const int nch = ((t + 1) * BM + KC - 1) / KC;
    const size_t base0 = (((size_t)b * NT + t) * MAXCH) * BM + row;

    float mc[MAXCH], lc[MAXCH];
    float mstar = -INFINITY;
    for (int c = 0; c < nch; c++) {
        float2 ml = *(const float2*)&g_pml[(base0 + (size_t)c * BM) * 2];
        mc[c] = ml.x; lc[c] = ml.y;
        mstar = fmaxf(mstar, ml.x);
    }

    float lsum = 0.f;
    float4 o = make_float4(0.f, 0.f, 0.f, 0.f);

    for (int c = 0; c < nch; c++) {
        float w = __expf(mc[c] - mstar);
        lsum += lc[c] * w;
        float4 v4 = *(const float4*)(g_po + (base0 + (size_t)c * BM) * DK + f4 * 4);
        o.x = fmaf(w, v4.x, o.x);
        o.y = fmaf(w, v4.y, o.y);
        o.z = fmaf(w, v4.z, o.z);
        o.w = fmaf(w, v4.w, o.w);
    }
    float inv = 1.f / lsum;
    *(float4*)(g_ho + ((size_t)b * S_LEN + t * BM + row) * DK + f4 * 4) =
        make_float4(o.x * inv, o.y * inv, o.z * inv, o.w * inv);
}

// ------------------------- 5) output GEMM: ho @ W_eff + Wo_b ------------------
// out[8192,512] = ho[8192,64] @ g_weff[64,512] + b. (R7 form — known best)
__global__ __launch_bounds__(256) void outproj_kernel(
    const float* __restrict__ Wo_b, float* __restrict__ out)
{
    __shared__ float As[64][65];
    __shared__ float Bs[64][64];

    const int tid = threadIdx.x;
    const int tx = tid & 15, ty = tid >> 4;
    const int m0 = blockIdx.x * 64;
    const int n0 = blockIdx.y * 64;

    #pragma unroll
    for (int it = 0; it < 4; it++) {
        int idx = tid + it * 256;
        int row = idx >> 4;
        int c4  = idx & 15;
        float4 v4 = *(const float4*)(g_ho + (size_t)(m0 + row) * DK + c4 * 4);
        As[row][c4 * 4 + 0] = v4.x; As[row][c4 * 4 + 1] = v4.y;
        As[row][c4 * 4 + 2] = v4.z; As[row][c4 * 4 + 3] = v4.w;
    }
    #pragma unroll
    for (int it = 0; it < 4; it++) {
        int idx = tid + it * 256;
        int row = idx >> 4;
        int c4  = idx & 15;
        float4 v4 = *(const float4*)(g_weff + (size_t)row * DMODEL + n0 + c4 * 4);
        *(float4*)&Bs[row][c4 * 4] = v4;
    }
    __syncthreads();

    u64 acc2[4][2];
    #pragma unroll
    for (int i = 0; i < 4; i++) { acc2[i][0] = 0ull; acc2[i][1] = 0ull; }

    #pragma unroll
    for (int kk = 0; kk < 64; kk++) {
        u64 pa0 = pack2(As[ty * 4 + 0][kk], As[ty * 4 + 0][kk]);
        u64 pa1 = pack2(As[ty * 4 + 1][kk], As[ty * 4 + 1][kk]);
        u64 pa2 = pack2(As[ty * 4 + 2][kk], As[ty * 4 + 2][kk]);
        u64 pa3 = pack2(As[ty * 4 + 3][kk], As[ty * 4 + 3][kk]);
        ulonglong2 b2 = *(const ulonglong2*)&Bs[kk][tx * 4];
        ffma2(acc2[0][0], pa0, b2.x); ffma2(acc2[0][1], pa0, b2.y);
        ffma2(acc2[1][0], pa1, b2.x); ffma2(acc2[1][1], pa1, b2.y);
        ffma2(acc2[2][0], pa2, b2.x); ffma2(acc2[2][1], pa2, b2.y);
        ffma2(acc2[3][0], pa3, b2.x); ffma2(acc2[3][1], pa3, b2.y);
    }

    float4 bb = *(const float4*)&Wo_b[n0 + tx * 4];
    #pragma unroll
    for (int i = 0; i < 4; i++) {
        float2 c0 = unpack2(acc2[i][0]);
        float2 c1 = unpack2(acc2[i][1]);
        float4 r = make_float4(c0.x + bb.x, c0.y + bb.y, c1.x + bb.z, c1.y + bb.w);
        *(float4*)&out[(size_t)(m0 + ty * 4 + i) * DMODEL + n0 + tx * 4] = r;
    }
}

// ------------------------- launch --------------------------------------------
extern "C" void kernel_launch(void* const* d_in, const int* in_sizes, int n_in,
                              void* d_out, int out_size) {
    const float* Q    = (const float*)d_in[0];
    const float* K    = (const float*)d_in[1];
    const float* V    = (const float*)d_in[2];
    const float* WQ_w = (const float*)d_in[3];
    const float* WQ_b = (const float*)d_in[4];
    const float* WK_w = (const float*)d_in[5];
    const float* WK_b = (const float*)d_in[6];
    const float* WV_w = (const float*)d_in[7];
    const float* WV_b = (const float*)d_in[8];
    const float* Wo_w = (const float*)d_in[9];
    const float* Wo_b = (const float*)d_in[10];
    float* out = (float*)d_out;

    dim3 gproj(B_SZ * S_LEN / 64, 1, 3);
    proj_kernel<<<gproj, 256>>>(Q, K, V, WQ_w, WQ_b, WK_w, WK_b, WV_w, WV_b);

    weff_kernel<<<(DK * DMODEL) / 256, 256>>>(Wo_w);

    dim3 gattn(MAXCH, NT, B_SZ);
    attn_partial_kernel<<<gattn, 128>>>();

    dim3 gmerge(NT * 2, B_SZ);
    attn_merge_kernel<<<gmerge, 1024>>>();

    dim3 gout(B_SZ * S_LEN / 64, DMODEL / 64);
    outproj_kernel<<<gout, 256>>>(Wo_b, out);
}